// round 14
// baseline (speedup 1.0000x reference)
#include <cuda_runtime.h>
#include <cuda_fp16.h>
#include <math.h>
#include <stdint.h>

// Problem constants
#define BB   4
#define LL   1024
#define DD   1024
#define NH   16
#define HH   64
#define RR   2048
#define LOG2E 1.4426950408889634f
#define KBYTES 2048        // K=1024 fp16 row stride in bytes

// ---------------------------------------------------------------------------
// Device scratch
// ---------------------------------------------------------------------------
__device__ uint4 g_IN4[BB * LL * DD / 8];      // 8 MB fp16 (attn output staging)
__device__ uint4 g_WT4[5 * DD * DD / 8];       // 10 MB fp16 weights, 5 slots [n][k]

__device__ uint32_t g_QH2[BB * NH * LL * HH / 2];
__device__ uint32_t g_KH2[BB * NH * LL * HH / 2];
__device__ uint32_t g_VH2[BB * NH * LL * HH / 2];
__device__ uint32_t g_RP2[NH * RR * HH / 2];
__device__ float    g_C1[BB * NH * LL];
__device__ float    g_C2[NH * RR];

__device__ __forceinline__ uint32_t smem_u32(const void* p) {
    uint32_t a;
    asm("{ .reg .u64 t; cvta.to.shared.u64 t, %1; cvt.u32.u64 %0, t; }" : "=r"(a) : "l"(p));
    return a;
}
__device__ __forceinline__ void ldmx4(uint32_t* r, uint32_t addr) {
    asm volatile("ldmatrix.sync.aligned.m8n8.x4.shared.b16 {%0,%1,%2,%3}, [%4];"
        : "=r"(r[0]), "=r"(r[1]), "=r"(r[2]), "=r"(r[3]) : "r"(addr));
}
__device__ __forceinline__ void ldmx4t(uint32_t* r, uint32_t addr) {
    asm volatile("ldmatrix.sync.aligned.m8n8.x4.trans.shared.b16 {%0,%1,%2,%3}, [%4];"
        : "=r"(r[0]), "=r"(r[1]), "=r"(r[2]), "=r"(r[3]) : "r"(addr));
}
__device__ __forceinline__ void mma16816(float* c, const uint32_t* a, const uint32_t* b) {
    asm volatile("mma.sync.aligned.m16n8k16.row.col.f32.f16.f16.f32 "
        "{%0,%1,%2,%3}, {%4,%5,%6,%7}, {%8,%9}, {%0,%1,%2,%3};"
        : "+f"(c[0]), "+f"(c[1]), "+f"(c[2]), "+f"(c[3])
        : "r"(a[0]), "r"(a[1]), "r"(a[2]), "r"(a[3]), "r"(b[0]), "r"(b[1]));
}
#define CPA16(dst, src) \
    asm volatile("cp.async.cg.shared.global [%0], [%1], 16;" :: "r"(dst), "l"(src) : "memory")
#define CP_COMMIT() asm volatile("cp.async.commit_group;" ::: "memory")
#define CP_WAIT(n)  asm volatile("cp.async.wait_group %0;" :: "n"(n) : "memory")

__device__ __forceinline__ uint32_t pack_h2(float a, float b) {
    __half2 h2; h2.x = __float2half_rn(a); h2.y = __float2half_rn(b);
    return *(uint32_t*)&h2;
}
__device__ __forceinline__ uint4 cvt8(float4 a, float4 b) {
    uint4 r;
    r.x = pack_h2(a.x, a.y); r.y = pack_h2(a.z, a.w);
    r.z = pack_h2(b.x, b.y); r.w = pack_h2(b.z, b.w);
    return r;
}
// exp2 on FMA pipe: deg-5 poly + exponent splice.  arg <= 0, clamped at -125.
__device__ __forceinline__ float exp2p(float t) {
    t = fmaxf(t, -125.0f);
    float tr = t + 12582912.0f;
    int   n  = __float_as_int(tr) - 0x4B400000;
    float f  = t - (tr - 12582912.0f);
    float p  = 1.3333558146e-3f;
    p = fmaf(p, f, 9.6181291076e-3f);
    p = fmaf(p, f, 5.5504108665e-2f);
    p = fmaf(p, f, 2.4022650696e-1f);
    p = fmaf(p, f, 6.9314718056e-1f);
    p = fmaf(p, f, 1.0f);
    return __int_as_float(__float_as_int(p) + (n << 23));
}

// ---------------------------------------------------------------------------
// Weight transposes.  trcvt4: 4 square 1024x1024 weights in one launch.
// ---------------------------------------------------------------------------
__global__ void trcvt4_kernel(const float* __restrict__ w0, const float* __restrict__ w1,
                              const float* __restrict__ w2, const float* __restrict__ w3,
                              __half* __restrict__ dbase)
{
    __shared__ float t[32][33];
    const int bz = blockIdx.z;
    const float* s = (bz == 0) ? w0 : (bz == 1) ? w1 : (bz == 2) ? w2 : w3;
    __half* d = dbase + (size_t)bz * DD * DD;
    const int c0 = blockIdx.x * 32, r0 = blockIdx.y * 32;
    const int tx = threadIdx.x, ty = threadIdx.y;
#pragma unroll
    for (int i = 0; i < 4; i++)
        t[ty + 8 * i][tx] = s[(size_t)(r0 + ty + 8 * i) * DD + c0 + tx];
    __syncthreads();
#pragma unroll
    for (int i = 0; i < 4; i++)
        d[(size_t)(c0 + ty + 8 * i) * DD + r0 + tx] = __float2half_rn(t[tx][ty + 8 * i]);
}

// generic transpose-convert (used for r_kernel: src [bz][R][C] -> dst [bz][C][R])
__global__ void trcvt_kernel(const float* __restrict__ src,
                             __half* __restrict__ dstv, int R, int C)
{
    __shared__ float t[32][33];
    const int bz = blockIdx.z;
    const int c0 = blockIdx.x * 32, r0 = blockIdx.y * 32;
    const int tx = threadIdx.x, ty = threadIdx.y;
    const float* s = src + (size_t)bz * R * C;
#pragma unroll
    for (int i = 0; i < 4; i++)
        t[ty + 8 * i][tx] = s[(size_t)(r0 + ty + 8 * i) * C + c0 + tx];
    __syncthreads();
#pragma unroll
    for (int i = 0; i < 4; i++) {
        float v = t[tx][ty + 8 * i];
        size_t o = (size_t)bz * C * R + (size_t)(c0 + ty + 8 * i) * R + r0 + tx;
        dstv[o] = __float2half_rn(v);
    }
}

// Bias-correction dot products
__global__ __launch_bounds__(256) void cdot_kernel(
    const uint32_t* __restrict__ x2, const float* __restrict__ wvec,
    float* __restrict__ outv, int sel)
{
    __shared__ float w[64];
    const int row = blockIdx.x * 256 + threadIdx.x;
    const int n = (sel == 10) ? ((row >> 10) & 15) : (row >> 11);
    if (threadIdx.x < 64) w[threadIdx.x] = wvec[n * 64 + threadIdx.x];
    __syncthreads();
    float s = 0.f;
    const uint32_t* ph = x2 + (size_t)row * 32;
#pragma unroll 8
    for (int i = 0; i < 32; i++) {
        uint32_t h = ph[i];
        __half2 hb = *(__half2*)&h;
        s += __half2float(hb.x) * w[i * 2] + __half2float(hb.y) * w[i * 2 + 1];
    }
    outv[row] = s;
}

// ---------------------------------------------------------------------------
// HMMA GEMM fp16.  A is fp32 (converted while staging) except mode 3 (fp16).
// mode 0: z-batched qkv.  A = [A0f,A1f,A2f][z], W slot z, out [o0,o1,o2][z],
//         bias [null, x1, x2][z], bnlh half2 epilogue.
// mode 3: A = Ah fp16 (attn output), W slot 3, fp32 out0 = D + pb + resid.
// mode 4: A = A0f fp32 (pos_enc), W slot 4, rp-layout half2 epilogue.
// ---------------------------------------------------------------------------
#define STRIDE 80

__global__ __launch_bounds__(256) void hgemm(
    const float* __restrict__ A0f, const float* __restrict__ A1f,
    const float* __restrict__ A2f, const char* __restrict__ Ah,
    const __half* __restrict__ Wb,
    const float* __restrict__ x1, const float* __restrict__ x2,
    const float* __restrict__ pb, const float* __restrict__ resid,
    float* __restrict__ out0,
    uint32_t* __restrict__ o0, uint32_t* __restrict__ o1, uint32_t* __restrict__ o2,
    int mode)
{
    __shared__ char sA[128 * STRIDE];
    __shared__ char sB[128 * STRIDE];

    const int z = blockIdx.z;
    const int tid = threadIdx.x, lane = tid & 31, wid = tid >> 5;
    const int wm = wid >> 1, wn = wid & 1;
    const int m0 = blockIdx.y * 128, n0 = blockIdx.x * 128;

    const float* Af = (mode == 0) ? (z == 0 ? A0f : (z == 1 ? A1f : A2f)) : A0f;
    const int wslot  = (mode == 0) ? z : (mode == 3 ? 3 : 4);
    const char* Bm   = (const char*)(Wb + (size_t)wslot * DD * DD);
    const bool afp32 = (mode != 3);

    float c[2][8][4] = {};

    const int lrow = tid >> 1, lseg = (tid & 1) * 32;    // fp16-byte offset
    const float* gAf = Af ? (Af + (size_t)(m0 + lrow) * DD + (tid & 1) * 16) : nullptr;
    const char*  gAh = Ah ? (Ah + (size_t)(m0 + lrow) * KBYTES + lseg) : nullptr;
    const char*  gpB = Bm + (size_t)(n0 + lrow) * KBYTES + lseg;
    const int srow = lrow * STRIDE + lseg;
    char* spA = sA + srow;
    char* spB = sB + srow;

    const uint32_t aBase = smem_u32(sA);
    const uint32_t bBase = smem_u32(sB);
    const int arow_in = (lane & 7) + ((lane >> 3) & 1) * 8;
    const int ak16    = (lane >> 4) * 16;
    const int brow_in = (lane & 7) + (lane >> 4) * 8;
    const int bk16    = ((lane >> 3) & 1) * 16;
    const uint32_t aOff = aBase + (wm * 32 + arow_in) * STRIDE + ak16;
    const uint32_t bOff = bBase + (wn * 64 + brow_in) * STRIDE + bk16;

    uint4 pfa0, pfa1, pfb0, pfb1;
    if (afp32) {
        float4 f0 = *(const float4*)(gAf + 0), f1 = *(const float4*)(gAf + 4);
        float4 f2 = *(const float4*)(gAf + 8), f3 = *(const float4*)(gAf + 12);
        pfa0 = cvt8(f0, f1); pfa1 = cvt8(f2, f3);
    } else {
        pfa0 = *(const uint4*)(gAh); pfa1 = *(const uint4*)(gAh + 16);
    }
    pfb0 = *(const uint4*)(gpB);  pfb1 = *(const uint4*)(gpB + 16);

    for (int ck = 0; ck < 32; ck++) {
        *(uint4*)(spA) = pfa0; *(uint4*)(spA + 16) = pfa1;
        *(uint4*)(spB) = pfb0; *(uint4*)(spB + 16) = pfb1;
        __syncthreads();
        if (ck < 31) {
            const int offh = (ck + 1) * 64;            // fp16 bytes
            const int offf = (ck + 1) * 32;            // fp32 elements
            if (afp32) {
                float4 f0 = *(const float4*)(gAf + offf + 0);
                float4 f1 = *(const float4*)(gAf + offf + 4);
                float4 f2 = *(const float4*)(gAf + offf + 8);
                float4 f3 = *(const float4*)(gAf + offf + 12);
                pfa0 = cvt8(f0, f1); pfa1 = cvt8(f2, f3);
            } else {
                pfa0 = *(const uint4*)(gAh + offh); pfa1 = *(const uint4*)(gAh + offh + 16);
            }
            pfb0 = *(const uint4*)(gpB + offh); pfb1 = *(const uint4*)(gpB + offh + 16);
        }
#pragma unroll
        for (int ks = 0; ks < 2; ks++) {
            const int kb = ks * 32;
            uint32_t ah[2][4];
#pragma unroll
            for (int mt = 0; mt < 2; mt++)
                ldmx4(ah[mt], aOff + mt * (16 * STRIDE) + kb);
#pragma unroll
            for (int ntp = 0; ntp < 4; ntp++) {
                uint32_t bh[4];
                ldmx4(bh, bOff + ntp * (16 * STRIDE) + kb);
#pragma unroll
                for (int mt = 0; mt < 2; mt++) {
                    mma16816(c[mt][ntp * 2 + 0], ah[mt], bh + 0);
                    mma16816(c[mt][ntp * 2 + 1], ah[mt], bh + 2);
                }
            }
        }
        __syncthreads();
    }

    const float* aux = (mode == 0) ? (z == 0 ? nullptr : (z == 1 ? x1 : x2)) : pb;
    uint32_t* oq = (mode == 0) ? (z == 0 ? o0 : (z == 1 ? o1 : o2)) : o0;

    const int g = lane >> 2, tg = lane & 3;
#pragma unroll
    for (int mt = 0; mt < 2; mt++) {
#pragma unroll
        for (int half = 0; half < 2; half++) {
            const int m = m0 + wm * 32 + mt * 16 + g + half * 8;
#pragma unroll
            for (int nt = 0; nt < 8; nt++) {
                float v0 = c[mt][nt][half * 2 + 0];
                float v1 = c[mt][nt][half * 2 + 1];
                const int coln = n0 + wn * 64 + nt * 8 + tg * 2;
                if (mode == 3) {
                    size_t o = (size_t)m * DD + coln;
                    float2 res = *(const float2*)(resid + o);
                    *(float2*)(out0 + o) =
                        make_float2(v0 + aux[coln] + res.x, v1 + aux[coln + 1] + res.y);
                } else if (mode == 4) {
                    int hd = coln >> 6, h = coln & 63;
                    size_t o = ((size_t)hd * RR + m) * HH + h;
                    oq[o >> 1] = pack_h2(v0, v1);
                } else {
                    int hd = coln >> 6, h = coln & 63;
                    int b = m >> 10, l = m & 1023;
                    size_t o = ((size_t)(b * NH + hd) * LL + l) * HH + h;
                    float b0 = aux ? aux[coln] : 0.f;
                    float b1 = aux ? aux[coln + 1] : 0.f;
                    oq[o >> 1] = pack_h2(v0 + b0, v1 + b1);
                }
            }
        }
    }
}

// ---------------------------------------------------------------------------
// HMMA flash attention (unchanged from R12)
// ---------------------------------------------------------------------------
#define AST     144
#define POSW2   84
#define OFF_K   0
#define OFF_V   9216
#define OFF_R   18432
#define OFF_POS 46080
#define OFF_CC  89088
#define OFF_C2  89344
#define ATTN_BYTES 90112
#define SCALE2F (0.125f * LOG2E)

__global__ __launch_bounds__(256) void attn2(const int* __restrict__ pad,
    const float* __restrict__ c1g, const float* __restrict__ c2g,
    const uint32_t* __restrict__ qh2, const uint32_t* __restrict__ kh2,
    const uint32_t* __restrict__ vh2, const uint32_t* __restrict__ rp2,
    uint32_t* __restrict__ outp)
{
    extern __shared__ char dyn[];
    float* pos = (float*)(dyn + OFF_POS);
    float* cc  = (float*)(dyn + OFF_CC);
    float* c2s = (float*)(dyn + OFF_C2);

    const int tid = threadIdx.x, lane = tid & 31, w = tid >> 5;
    const int g = lane >> 2, tg = lane & 3;
    const int bn = blockIdx.y, b = bn >> 4, n = bn & 15;
    const int l0 = blockIdx.x * 128;

    const uint32_t uD = smem_u32(dyn);
    const uint32_t uK = uD + OFF_K, uV = uD + OFF_V, uR = uD + OFF_R;

    const int arow = (lane & 7) + ((lane >> 3) & 1) * 8;
    const int ak16 = (lane >> 4) * 16;
    const int brow = (lane & 7) + (lane >> 4) * 8;
    const int bk16 = ((lane >> 3) & 1) * 16;
    const int vrow = (lane & 7) + ((lane >> 3) & 1) * 8;
    const int vsel = (lane >> 4) * 16;

    {
        const int lrowQ = tid >> 1, lsegQ = (tid & 1) * 64;
        const size_t qoff = ((size_t)(bn * LL + l0 + lrowQ) << 7) + lsegQ;
        const uint4* s = (const uint4*)((const char*)qh2 + qoff);
        uint4* d = (uint4*)(dyn + OFF_R + lrowQ * AST + lsegQ);
        d[0] = s[0]; d[1] = s[1]; d[2] = s[2]; d[3] = s[3];
    }
    __syncthreads();
    uint32_t fqh[4][4];
    {
        const uint32_t ao = uR + (w * 16 + arow) * AST + ak16;
#pragma unroll
        for (int ks = 0; ks < 4; ks++)
            ldmx4(fqh[ks], ao + ks * 32);
    }

    float o[8][4] = {};
    float mrow[2] = {-INFINITY, -INFINITY};
    float lrowv[2] = {0.f, 0.f};

    for (int kt = 0; kt < LL / 64; kt++) {
        const int m0 = kt * 64;
        const int rel0 = LL + m0 - l0 - 127;
        const int roff = (kt % 3) * 64;

        __syncthreads();
        {
            const int lrow4 = tid >> 2, lseg4 = (tid & 3) * 32;
            const size_t kv = ((size_t)(bn * LL + m0 + lrow4) << 7) + lseg4;
            const uint32_t dr = uD + lrow4 * AST + lseg4;
            const char* s;
            s = (const char*)kh2 + kv;
            CPA16(dr + OFF_K, s); CPA16(dr + OFF_K + 16, s + 16);
            s = (const char*)vh2 + kv;
            CPA16(dr + OFF_V, s); CPA16(dr + OFF_V + 16, s + 16);
            if (kt == 0) {
#pragma unroll
                for (int cch = 0; cch < 3; cch++) {
                    const int rowl = cch * 64 + lrow4;
                    int rel = rel0 + rowl;
                    rel = rel < 0 ? 0 : (rel > RR - 1 ? RR - 1 : rel);
                    const char* rs = (const char*)rp2 + (((size_t)(n * RR + rel)) << 7) + lseg4;
                    uint32_t rd = uR + rowl * AST + lseg4;
                    CPA16(rd, rs); CPA16(rd + 16, rs + 16);
                }
            } else {
                int rel = rel0 + 128 + lrow4;
                rel = rel < 0 ? 0 : (rel > RR - 1 ? RR - 1 : rel);
                const int phys = (128 + roff) % 192 + lrow4;
                const char* rs = (const char*)rp2 + (((size_t)(n * RR + rel)) << 7) + lseg4;
                uint32_t rd = uR + phys * AST + lseg4;
                CPA16(rd, rs); CPA16(rd + 16, rs + 16);
            }
            CP_COMMIT();
            if (tid < 64)
                cc[tid] = c1g[(size_t)bn * LL + m0 + tid] * SCALE2F +
                          (pad[b * LL + m0 + tid] ? (-1.0e6f * LOG2E) : 0.0f);
            if (tid < 192) {
                int rel = rel0 + tid;
                rel = rel < 0 ? 0 : (rel > RR - 1 ? RR - 1 : rel);
                c2s[tid] = c2g[n * RR + rel];
            }
        }
        CP_WAIT(0);
        __syncthreads();

#pragma unroll
        for (int npi = 0; npi < 5; npi++) {
            const int np = npi + 7 - w;
            float b0[4] = {}, b1[4] = {};
            int pr16 = np * 16 + roff;
            if (pr16 >= 192) pr16 -= 192;
            const uint32_t rbase = (pr16 + brow) * AST + bk16;
#pragma unroll
            for (int ks = 0; ks < 4; ks++) {
                uint32_t bh[4];
                ldmx4(bh, uR + rbase + ks * 32);
                mma16816(b0, fqh[ks], bh + 0);
                mma16816(b1, fqh[ks], bh + 2);
            }
            const int pc   = npi * 16 + tg * 2;
            const int cidx = np * 16 + tg * 2;
            float* pr0 = pos + (w * 16 + g) * POSW2;
            float* pr1 = pos + (w * 16 + g + 8) * POSW2;
            const float ca = c2s[cidx],     cb = c2s[cidx + 1];
            const float cd = c2s[cidx + 8], ce = c2s[cidx + 9];
            *(float2*)(pr0 + pc)     = make_float2(b0[0] + ca, b0[1] + cb);
            *(float2*)(pr1 + pc)     = make_float2(b0[2] + ca, b0[3] + cb);
            *(float2*)(pr0 + pc + 8) = make_float2(b1[0] + cd, b1[1] + ce);
            *(float2*)(pr1 + pc + 8) = make_float2(b1[2] + cd, b1[3] + ce);
        }

        float sfr[8][4] = {};
#pragma unroll
        for (int ks = 0; ks < 4; ks++) {
#pragma unroll
            for (int np = 0; np < 4; np++) {
                uint32_t bh[4];
                ldmx4(bh, uK + (np * 16 + brow) * AST + bk16 + ks * 32);
                mma16816(sfr[np * 2 + 0], fqh[ks], bh + 0);
                mma16816(sfr[np * 2 + 1], fqh[ks], bh + 2);
            }
        }
        __syncwarp();

#pragma unroll
        for (int r2 = 0; r2 < 2; r2++) {
            const int ii = g + r2 * 8;
            const float* pr = pos + (w * 16 + ii) * POSW2 + (15 - ii);
            float mx = -INFINITY;
#pragma unroll
            for (int nt = 0; nt < 8; nt++) {
#pragma unroll
                for (int v2 = 0; v2 < 2; v2++) {
                    const int j = nt * 8 + tg * 2 + v2;
                    float t = fmaf(sfr[nt][r2 * 2 + v2] + pr[j], SCALE2F, cc[j]);
                    sfr[nt][r2 * 2 + v2] = t;
                    mx = fmaxf(mx, t);
                }
            }
            mx = fmaxf(mx, __shfl_xor_sync(0xffffffffu, mx, 1));
            mx = fmaxf(mx, __shfl_xor_sync(0xffffffffu, mx, 2));
            const float mnew = fmaxf(mrow[r2], mx);
            const float alpha = exp2p(mrow[r2] - mnew);
            mrow[r2] = mnew;
            float ssum = 0.f;
#pragma unroll
            for (int nt = 0; nt < 8; nt++) {
#pragma unroll
                for (int v2 = 0; v2 < 2; v2++) {
                    float p = exp2p(sfr[nt][r2 * 2 + v2] - mnew);
                    sfr[nt][r2 * 2 + v2] = p;
                    ssum += p;
                }
            }
            ssum += __shfl_xor_sync(0xffffffffu, ssum, 1);
            ssum += __shfl_xor_sync(0xffffffffu, ssum, 2);
            lrowv[r2] = lrowv[r2] * alpha + ssum;
#pragma unroll
            for (int ht = 0; ht < 8; ht++) {
                o[ht][r2 * 2 + 0] *= alpha;
                o[ht][r2 * 2 + 1] *= alpha;
            }
        }

#pragma unroll
        for (int ks = 0; ks < 4; ks++) {
            uint32_t aph[4];
#pragma unroll
            for (int q2 = 0; q2 < 2; q2++) {
                const float* f = sfr[2 * ks + q2];
                aph[q2 * 2 + 0] = pack_h2(f[0], f[1]);
                aph[q2 * 2 + 1] = pack_h2(f[2], f[3]);
            }
            const uint32_t vo = (ks * 16 + vrow) * AST + vsel;
#pragma unroll
            for (int hp = 0; hp < 4; hp++) {
                uint32_t vbh[4];
                ldmx4t(vbh, uV + vo + hp * 32);
                mma16816(o[hp * 2 + 0], aph, vbh + 0);
                mma16816(o[hp * 2 + 1], aph, vbh + 2);
            }
        }
    }

#pragma unroll
    for (int r2 = 0; r2 < 2; r2++) {
        const int i = w * 16 + g + r2 * 8;
        const int rowg = b * LL + l0 + i;
        const float inv = 1.0f / lrowv[r2];
#pragma unroll
        for (int ht = 0; ht < 8; ht++) {
            float v0 = o[ht][r2 * 2 + 0] * inv;
            float v1 = o[ht][r2 * 2 + 1] * inv;
            const int col = n * 64 + ht * 8 + tg * 2;
            outp[(size_t)rowg * 512 + (col >> 1)] = pack_h2(v0, v1);
        }
    }
}

// ---------------------------------------------------------------------------
// LayerNorm
// ---------------------------------------------------------------------------
__global__ __launch_bounds__(256) void ln_kernel(
    float* __restrict__ X, const float* __restrict__ g, const float* __restrict__ bta)
{
    __shared__ float red[8];
    const int row = blockIdx.x;
    const int t   = threadIdx.x;
    float4 x = *(float4*)(X + (size_t)row * DD + t * 4);

    float s = x.x + x.y + x.z + x.w;
#pragma unroll
    for (int d = 16; d; d >>= 1) s += __shfl_xor_sync(0xffffffffu, s, d);
    if ((t & 31) == 0) red[t >> 5] = s;
    __syncthreads();
    float tot = red[0] + red[1] + red[2] + red[3] + red[4] + red[5] + red[6] + red[7];
    float mu = tot * (1.0f / DD);
    __syncthreads();

    float dx0 = x.x - mu, dx1 = x.y - mu, dx2 = x.z - mu, dx3 = x.w - mu;
    float sq = dx0 * dx0 + dx1 * dx1 + dx2 * dx2 + dx3 * dx3;
#pragma unroll
    for (int d = 16; d; d >>= 1) sq += __shfl_xor_sync(0xffffffffu, sq, d);
    if ((t & 31) == 0) red[t >> 5] = sq;
    __syncthreads();
    float var = (red[0] + red[1] + red[2] + red[3] + red[4] + red[5] + red[6] + red[7]) * (1.0f / DD);
    float rs = rsqrtf(var + 1e-5f);

    float4 gg = *(const float4*)(g + t * 4);
    float4 bb = *(const float4*)(bta + t * 4);
    float4 y = make_float4(dx0 * rs * gg.x + bb.x, dx1 * rs * gg.y + bb.y,
                           dx2 * rs * gg.z + bb.z, dx3 * rs * gg.w + bb.w);
    *(float4*)(X + (size_t)row * DD + t * 4) = y;
}

// ---------------------------------------------------------------------------
// Launch
// ---------------------------------------------------------------------------
extern "C" void kernel_launch(void* const* d_in, const int* in_sizes, int n_in,
                              void* d_out, int out_size)
{
    const float* q   = (const float*)d_in[0];
    const float* k   = (const float*)d_in[1];
    const float* v   = (const float*)d_in[2];
    const float* pe  = (const float*)d_in[3];
    const int*   pad = (const int*)d_in[4];
    const float* q_w = (const float*)d_in[5];
    const float* k_w = (const float*)d_in[6];
    const float* k_b = (const float*)d_in[7];
    const float* v_w = (const float*)d_in[8];
    const float* v_b = (const float*)d_in[9];
    const float* rwb = (const float*)d_in[10];
    const float* rrb = (const float*)d_in[11];
    const float* r_k = (const float*)d_in[12];
    const float* pw  = (const float*)d_in[13];
    const float* pb  = (const float*)d_in[14];
    const float* lg  = (const float*)d_in[15];
    const float* lb  = (const float*)d_in[16];
    float* out = (float*)d_out;

    cudaFuncSetAttribute(attn2, cudaFuncAttributeMaxDynamicSharedMemorySize, ATTN_BYTES);

    char *inp, *wtp;
    cudaGetSymbolAddress((void**)&inp, g_IN4);
    cudaGetSymbolAddress((void**)&wtp, g_WT4);
    uint32_t *qh2, *kh2, *vh2, *rp2;
    float *c1p, *c2p;
    cudaGetSymbolAddress((void**)&qh2, g_QH2);
    cudaGetSymbolAddress((void**)&kh2, g_KH2);
    cudaGetSymbolAddress((void**)&vh2, g_VH2);
    cudaGetSymbolAddress((void**)&rp2, g_RP2);
    cudaGetSymbolAddress((void**)&c1p, g_C1);
    cudaGetSymbolAddress((void**)&c2p, g_C2);

    dim3 tr(32, 8);

    // 1. weight transposes: q_w,k_w,v_w,pw -> slots 0..3; r_kernel -> slot 4
    trcvt4_kernel<<<dim3(32, 32, 4), tr>>>(q_w, k_w, v_w, pw, (__half*)wtp);
    trcvt_kernel<<<dim3(2, 32, 16), tr>>>(r_k, (__half*)wtp + (size_t)4 * DD * DD, DD, HH);
    // 2. qkv projections, batched (fp32 A converted in-kernel)
    hgemm<<<dim3(8, 32, 3), 256>>>(q, k, v, nullptr, (const __half*)wtp,
                                   k_b, v_b, nullptr, nullptr, nullptr,
                                   qh2, kh2, vh2, 0);
    cdot_kernel<<<BB * NH * LL / 256, 256>>>(kh2, rwb, c1p, 10);
    // 3. rp projection (pe fp32)
    hgemm<<<dim3(8, 16, 1), 256>>>(pe, nullptr, nullptr, nullptr, (const __half*)wtp,
                                   nullptr, nullptr, nullptr, nullptr, nullptr,
                                   rp2, nullptr, nullptr, 4);
    cdot_kernel<<<NH * RR / 256, 256>>>(rp2, rrb, c2p, 11);
    // 4. attention
    attn2<<<dim3(LL / 128, BB * NH), 256, ATTN_BYTES>>>(pad, c1p, c2p, qh2,
                                                        kh2, vh2, rp2,
                                                        (uint32_t*)inp);
    // 5. post projection + residual (fp16 A from attn)
    hgemm<<<dim3(8, 32, 1), 256>>>(nullptr, nullptr, nullptr, inp, (const __half*)wtp,
                                   nullptr, nullptr, pb, q, out,
                                   nullptr, nullptr, nullptr, 3);
    // 6. layernorm
    ln_kernel<<<BB * LL, 256>>>(out, lg, lb);
}

// round 16
// speedup vs baseline: 1.1889x; 1.1889x over previous
#include <cuda_runtime.h>
#include <cuda_fp16.h>
#include <math.h>
#include <stdint.h>

// Problem constants
#define BB   4
#define LL   1024
#define DD   1024
#define NH   16
#define HH   64
#define RR   2048
#define LOG2E 1.4426950408889634f
#define KBYTES 2048        // K=1024 fp16 row stride in bytes

// ---------------------------------------------------------------------------
// Device scratch
// ---------------------------------------------------------------------------
__device__ uint4 g_A4[3 * BB * LL * DD / 8];   // 24 MB: fp16 q,k,v activations
__device__ uint4 g_PE4[RR * DD / 8];           // 4 MB: fp16 pos_enc
__device__ uint4 g_IN4[BB * LL * DD / 8];      // 8 MB: fp16 attn output
__device__ uint4 g_WT4[5 * DD * DD / 8];       // 10 MB fp16 weights, 5 slots [n][k]

__device__ uint32_t g_QH2[BB * NH * LL * HH / 2];
__device__ uint32_t g_KH2[BB * NH * LL * HH / 2];
__device__ uint32_t g_VH2[BB * NH * LL * HH / 2];
__device__ uint32_t g_RP2[NH * RR * HH / 2];
__device__ float    g_C1[BB * NH * LL];
__device__ float    g_C2[NH * RR];

__device__ __forceinline__ uint32_t smem_u32(const void* p) {
    uint32_t a;
    asm("{ .reg .u64 t; cvta.to.shared.u64 t, %1; cvt.u32.u64 %0, t; }" : "=r"(a) : "l"(p));
    return a;
}
__device__ __forceinline__ void ldmx4(uint32_t* r, uint32_t addr) {
    asm volatile("ldmatrix.sync.aligned.m8n8.x4.shared.b16 {%0,%1,%2,%3}, [%4];"
        : "=r"(r[0]), "=r"(r[1]), "=r"(r[2]), "=r"(r[3]) : "r"(addr));
}
__device__ __forceinline__ void ldmx4t(uint32_t* r, uint32_t addr) {
    asm volatile("ldmatrix.sync.aligned.m8n8.x4.trans.shared.b16 {%0,%1,%2,%3}, [%4];"
        : "=r"(r[0]), "=r"(r[1]), "=r"(r[2]), "=r"(r[3]) : "r"(addr));
}
__device__ __forceinline__ void mma16816(float* c, const uint32_t* a, const uint32_t* b) {
    asm volatile("mma.sync.aligned.m16n8k16.row.col.f32.f16.f16.f32 "
        "{%0,%1,%2,%3}, {%4,%5,%6,%7}, {%8,%9}, {%0,%1,%2,%3};"
        : "+f"(c[0]), "+f"(c[1]), "+f"(c[2]), "+f"(c[3])
        : "r"(a[0]), "r"(a[1]), "r"(a[2]), "r"(a[3]), "r"(b[0]), "r"(b[1]));
}
#define CPA16(dst, src) \
    asm volatile("cp.async.cg.shared.global [%0], [%1], 16;" :: "r"(dst), "l"(src) : "memory")
#define CP_COMMIT() asm volatile("cp.async.commit_group;" ::: "memory")
#define CP_WAIT(n)  asm volatile("cp.async.wait_group %0;" :: "n"(n) : "memory")

__device__ __forceinline__ uint32_t pack_h2(float a, float b) {
    __half2 h2; h2.x = __float2half_rn(a); h2.y = __float2half_rn(b);
    return *(uint32_t*)&h2;
}
// exp2 on FMA pipe: deg-5 poly + exponent splice.  arg <= 0, clamped at -125.
__device__ __forceinline__ float exp2p(float t) {
    t = fmaxf(t, -125.0f);
    float tr = t + 12582912.0f;
    int   n  = __float_as_int(tr) - 0x4B400000;
    float f  = t - (tr - 12582912.0f);
    float p  = 1.3333558146e-3f;
    p = fmaf(p, f, 9.6181291076e-3f);
    p = fmaf(p, f, 5.5504108665e-2f);
    p = fmaf(p, f, 2.4022650696e-1f);
    p = fmaf(p, f, 6.9314718056e-1f);
    p = fmaf(p, f, 1.0f);
    return __int_as_float(__float_as_int(p) + (n << 23));
}

// ---------------------------------------------------------------------------
// Prepass: batched fp32 -> fp16 conversion (z = 0..2: q/k/v -> g_A4 slots,
// z = 3: pos_enc -> g_PE4).
// ---------------------------------------------------------------------------
__global__ __launch_bounds__(256) void cvt4_kernel(
    const float4* __restrict__ s0, const float4* __restrict__ s1,
    const float4* __restrict__ s2, const float4* __restrict__ s3,
    uint32_t* __restrict__ abase, uint32_t* __restrict__ pebase)
{
    const int z = blockIdx.z;
    const int n4 = (z < 3) ? (BB * LL * DD / 4) : (RR * DD / 4);
    int i = blockIdx.x * 256 + threadIdx.x;
    if (i >= n4) return;
    const float4* src = (z == 0) ? s0 : (z == 1) ? s1 : (z == 2) ? s2 : s3;
    uint32_t* dst = (z < 3) ? (abase + (size_t)z * (BB * LL * DD / 2)) : pebase;
    float4 x = src[i];
    dst[i * 2 + 0] = pack_h2(x.x, x.y);
    dst[i * 2 + 1] = pack_h2(x.z, x.w);
}

// Batched square weight transposes: q_w,k_w,v_w,pw -> slots 0..3
__global__ void trcvt4_kernel(const float* __restrict__ w0, const float* __restrict__ w1,
                              const float* __restrict__ w2, const float* __restrict__ w3,
                              __half* __restrict__ dbase)
{
    __shared__ float t[32][33];
    const int bz = blockIdx.z;
    const float* s = (bz == 0) ? w0 : (bz == 1) ? w1 : (bz == 2) ? w2 : w3;
    __half* d = dbase + (size_t)bz * DD * DD;
    const int c0 = blockIdx.x * 32, r0 = blockIdx.y * 32;
    const int tx = threadIdx.x, ty = threadIdx.y;
#pragma unroll
    for (int i = 0; i < 4; i++)
        t[ty + 8 * i][tx] = s[(size_t)(r0 + ty + 8 * i) * DD + c0 + tx];
    __syncthreads();
#pragma unroll
    for (int i = 0; i < 4; i++)
        d[(size_t)(c0 + ty + 8 * i) * DD + r0 + tx] = __float2half_rn(t[tx][ty + 8 * i]);
}

// generic transpose-convert (r_kernel: [bz][R][C] -> [bz][C][R])
__global__ void trcvt_kernel(const float* __restrict__ src,
                             __half* __restrict__ dstv, int R, int C)
{
    __shared__ float t[32][33];
    const int bz = blockIdx.z;
    const int c0 = blockIdx.x * 32, r0 = blockIdx.y * 32;
    const int tx = threadIdx.x, ty = threadIdx.y;
    const float* s = src + (size_t)bz * R * C;
#pragma unroll
    for (int i = 0; i < 4; i++)
        t[ty + 8 * i][tx] = s[(size_t)(r0 + ty + 8 * i) * C + c0 + tx];
    __syncthreads();
#pragma unroll
    for (int i = 0; i < 4; i++) {
        float v = t[tx][ty + 8 * i];
        size_t o = (size_t)bz * C * R + (size_t)(c0 + ty + 8 * i) * R + r0 + tx;
        dstv[o] = __float2half_rn(v);
    }
}

// Bias-correction dot products
__global__ __launch_bounds__(256) void cdot_kernel(
    const uint32_t* __restrict__ x2, const float* __restrict__ wvec,
    float* __restrict__ outv, int sel)
{
    __shared__ float w[64];
    const int row = blockIdx.x * 256 + threadIdx.x;
    const int n = (sel == 10) ? ((row >> 10) & 15) : (row >> 11);
    if (threadIdx.x < 64) w[threadIdx.x] = wvec[n * 64 + threadIdx.x];
    __syncthreads();
    float s = 0.f;
    const uint32_t* ph = x2 + (size_t)row * 32;
#pragma unroll 8
    for (int i = 0; i < 32; i++) {
        uint32_t h = ph[i];
        __half2 hb = *(__half2*)&h;
        s += __half2float(hb.x) * w[i * 2] + __half2float(hb.y) * w[i * 2 + 1];
    }
    outv[row] = s;
}

// ---------------------------------------------------------------------------
// HMMA GEMM fp16 (R12 hot loop, z-batched dispatch).
// mode 0: z in 0..2 selects A slot / W slot / out / bias, bnlh half2 epilogue.
// mode 3: A = Ah (attn output), W slot 3, fp32 out = D + pb + resid.
// mode 4: A = pe16, W slot 4, rp layout half2 epilogue.
// ---------------------------------------------------------------------------
#define STRIDE 80

__global__ __launch_bounds__(256) void hgemm(
    const char* __restrict__ Abase, const char* __restrict__ Ah,
    const char* __restrict__ Pe16, const __half* __restrict__ Wb,
    const float* __restrict__ x1, const float* __restrict__ x2,
    const float* __restrict__ pb, const float* __restrict__ resid,
    float* __restrict__ out0,
    uint32_t* __restrict__ o0, uint32_t* __restrict__ o1, uint32_t* __restrict__ o2,
    int mode)
{
    __shared__ char sA[128 * STRIDE];
    __shared__ char sB[128 * STRIDE];

    const int z = blockIdx.z;
    const int tid = threadIdx.x, lane = tid & 31, wid = tid >> 5;
    const int wm = wid >> 1, wn = wid & 1;
    const int m0 = blockIdx.y * 128, n0 = blockIdx.x * 128;

    const char* Am = (mode == 0) ? (Abase + (size_t)z * (BB * LL * DD * 2))
                   : (mode == 3) ? Ah : Pe16;
    const int wslot = (mode == 0) ? z : (mode == 3 ? 3 : 4);
    const char* Bm  = (const char*)(Wb + (size_t)wslot * DD * DD);

    float c[2][8][4] = {};

    const int lrow = tid >> 1, lseg = (tid & 1) * 32;
    const char* gpA = Am + (size_t)(m0 + lrow) * KBYTES + lseg;
    const char* gpB = Bm + (size_t)(n0 + lrow) * KBYTES + lseg;
    const int srow = lrow * STRIDE + lseg;
    char* spA = sA + srow;
    char* spB = sB + srow;

    const uint32_t aBase = smem_u32(sA);
    const uint32_t bBase = smem_u32(sB);
    const int arow_in = (lane & 7) + ((lane >> 3) & 1) * 8;
    const int ak16    = (lane >> 4) * 16;
    const int brow_in = (lane & 7) + (lane >> 4) * 8;
    const int bk16    = ((lane >> 3) & 1) * 16;
    const uint32_t aOff = aBase + (wm * 32 + arow_in) * STRIDE + ak16;
    const uint32_t bOff = bBase + (wn * 64 + brow_in) * STRIDE + bk16;

    uint4 pfa0, pfa1, pfb0, pfb1;
    pfa0 = *(const uint4*)(gpA);  pfa1 = *(const uint4*)(gpA + 16);
    pfb0 = *(const uint4*)(gpB);  pfb1 = *(const uint4*)(gpB + 16);

    for (int ck = 0; ck < 32; ck++) {
        *(uint4*)(spA) = pfa0; *(uint4*)(spA + 16) = pfa1;
        *(uint4*)(spB) = pfb0; *(uint4*)(spB + 16) = pfb1;
        __syncthreads();
        if (ck < 31) {
            int off = (ck + 1) * 64;
            pfa0 = *(const uint4*)(gpA + off); pfa1 = *(const uint4*)(gpA + off + 16);
            pfb0 = *(const uint4*)(gpB + off); pfb1 = *(const uint4*)(gpB + off + 16);
        }
#pragma unroll
        for (int ks = 0; ks < 2; ks++) {
            const int kb = ks * 32;
            uint32_t ah[2][4];
#pragma unroll
            for (int mt = 0; mt < 2; mt++)
                ldmx4(ah[mt], aOff + mt * (16 * STRIDE) + kb);
#pragma unroll
            for (int ntp = 0; ntp < 4; ntp++) {
                uint32_t bh[4];
                ldmx4(bh, bOff + ntp * (16 * STRIDE) + kb);
#pragma unroll
                for (int mt = 0; mt < 2; mt++) {
                    mma16816(c[mt][ntp * 2 + 0], ah[mt], bh + 0);
                    mma16816(c[mt][ntp * 2 + 1], ah[mt], bh + 2);
                }
            }
        }
        __syncthreads();
    }

    const float* aux = (mode == 0) ? (z == 0 ? nullptr : (z == 1 ? x1 : x2)) : pb;
    uint32_t* oq = (mode == 0) ? (z == 0 ? o0 : (z == 1 ? o1 : o2)) : o0;

    const int g = lane >> 2, tg = lane & 3;
#pragma unroll
    for (int mt = 0; mt < 2; mt++) {
#pragma unroll
        for (int half = 0; half < 2; half++) {
            const int m = m0 + wm * 32 + mt * 16 + g + half * 8;
#pragma unroll
            for (int nt = 0; nt < 8; nt++) {
                float v0 = c[mt][nt][half * 2 + 0];
                float v1 = c[mt][nt][half * 2 + 1];
                const int coln = n0 + wn * 64 + nt * 8 + tg * 2;
                if (mode == 3) {
                    size_t o = (size_t)m * DD + coln;
                    float2 res = *(const float2*)(resid + o);
                    *(float2*)(out0 + o) =
                        make_float2(v0 + aux[coln] + res.x, v1 + aux[coln + 1] + res.y);
                } else if (mode == 4) {
                    int hd = coln >> 6, h = coln & 63;
                    size_t o = ((size_t)hd * RR + m) * HH + h;
                    oq[o >> 1] = pack_h2(v0, v1);
                } else {
                    int hd = coln >> 6, h = coln & 63;
                    int b = m >> 10, l = m & 1023;
                    size_t o = ((size_t)(b * NH + hd) * LL + l) * HH + h;
                    float b0 = aux ? aux[coln] : 0.f;
                    float b1 = aux ? aux[coln + 1] : 0.f;
                    oq[o >> 1] = pack_h2(v0 + b0, v1 + b1);
                }
            }
        }
    }
}

// ---------------------------------------------------------------------------
// HMMA flash attention (byte-identical to R12)
// ---------------------------------------------------------------------------
#define AST     144
#define POSW2   84
#define OFF_K   0
#define OFF_V   9216
#define OFF_R   18432
#define OFF_POS 46080
#define OFF_CC  89088
#define OFF_C2  89344
#define ATTN_BYTES 90112
#define SCALE2F (0.125f * LOG2E)

__global__ __launch_bounds__(256) void attn2(const int* __restrict__ pad,
    const float* __restrict__ c1g, const float* __restrict__ c2g,
    const uint32_t* __restrict__ qh2, const uint32_t* __restrict__ kh2,
    const uint32_t* __restrict__ vh2, const uint32_t* __restrict__ rp2,
    uint32_t* __restrict__ outp)
{
    extern __shared__ char dyn[];
    float* pos = (float*)(dyn + OFF_POS);
    float* cc  = (float*)(dyn + OFF_CC);
    float* c2s = (float*)(dyn + OFF_C2);

    const int tid = threadIdx.x, lane = tid & 31, w = tid >> 5;
    const int g = lane >> 2, tg = lane & 3;
    const int bn = blockIdx.y, b = bn >> 4, n = bn & 15;
    const int l0 = blockIdx.x * 128;

    const uint32_t uD = smem_u32(dyn);
    const uint32_t uK = uD + OFF_K, uV = uD + OFF_V, uR = uD + OFF_R;

    const int arow = (lane & 7) + ((lane >> 3) & 1) * 8;
    const int ak16 = (lane >> 4) * 16;
    const int brow = (lane & 7) + (lane >> 4) * 8;
    const int bk16 = ((lane >> 3) & 1) * 16;
    const int vrow = (lane & 7) + ((lane >> 3) & 1) * 8;
    const int vsel = (lane >> 4) * 16;

    {
        const int lrowQ = tid >> 1, lsegQ = (tid & 1) * 64;
        const size_t qoff = ((size_t)(bn * LL + l0 + lrowQ) << 7) + lsegQ;
        const uint4* s = (const uint4*)((const char*)qh2 + qoff);
        uint4* d = (uint4*)(dyn + OFF_R + lrowQ * AST + lsegQ);
        d[0] = s[0]; d[1] = s[1]; d[2] = s[2]; d[3] = s[3];
    }
    __syncthreads();
    uint32_t fqh[4][4];
    {
        const uint32_t ao = uR + (w * 16 + arow) * AST + ak16;
#pragma unroll
        for (int ks = 0; ks < 4; ks++)
            ldmx4(fqh[ks], ao + ks * 32);
    }

    float o[8][4] = {};
    float mrow[2] = {-INFINITY, -INFINITY};
    float lrowv[2] = {0.f, 0.f};

    for (int kt = 0; kt < LL / 64; kt++) {
        const int m0 = kt * 64;
        const int rel0 = LL + m0 - l0 - 127;
        const int roff = (kt % 3) * 64;

        __syncthreads();
        {
            const int lrow4 = tid >> 2, lseg4 = (tid & 3) * 32;
            const size_t kv = ((size_t)(bn * LL + m0 + lrow4) << 7) + lseg4;
            const uint32_t dr = uD + lrow4 * AST + lseg4;
            const char* s;
            s = (const char*)kh2 + kv;
            CPA16(dr + OFF_K, s); CPA16(dr + OFF_K + 16, s + 16);
            s = (const char*)vh2 + kv;
            CPA16(dr + OFF_V, s); CPA16(dr + OFF_V + 16, s + 16);
            if (kt == 0) {
#pragma unroll
                for (int cch = 0; cch < 3; cch++) {
                    const int rowl = cch * 64 + lrow4;
                    int rel = rel0 + rowl;
                    rel = rel < 0 ? 0 : (rel > RR - 1 ? RR - 1 : rel);
                    const char* rs = (const char*)rp2 + (((size_t)(n * RR + rel)) << 7) + lseg4;
                    uint32_t rd = uR + rowl * AST + lseg4;
                    CPA16(rd, rs); CPA16(rd + 16, rs + 16);
                }
            } else {
                int rel = rel0 + 128 + lrow4;
                rel = rel < 0 ? 0 : (rel > RR - 1 ? RR - 1 : rel);
                const int phys = (128 + roff) % 192 + lrow4;
                const char* rs = (const char*)rp2 + (((size_t)(n * RR + rel)) << 7) + lseg4;
                uint32_t rd = uR + phys * AST + lseg4;
                CPA16(rd, rs); CPA16(rd + 16, rs + 16);
            }
            CP_COMMIT();
            if (tid < 64)
                cc[tid] = c1g[(size_t)bn * LL + m0 + tid] * SCALE2F +
                          (pad[b * LL + m0 + tid] ? (-1.0e6f * LOG2E) : 0.0f);
            if (tid < 192) {
                int rel = rel0 + tid;
                rel = rel < 0 ? 0 : (rel > RR - 1 ? RR - 1 : rel);
                c2s[tid] = c2g[n * RR + rel];
            }
        }
        CP_WAIT(0);
        __syncthreads();

#pragma unroll
        for (int npi = 0; npi < 5; npi++) {
            const int np = npi + 7 - w;
            float b0[4] = {}, b1[4] = {};
            int pr16 = np * 16 + roff;
            if (pr16 >= 192) pr16 -= 192;
            const uint32_t rbase = (pr16 + brow) * AST + bk16;
#pragma unroll
            for (int ks = 0; ks < 4; ks++) {
                uint32_t bh[4];
                ldmx4(bh, uR + rbase + ks * 32);
                mma16816(b0, fqh[ks], bh + 0);
                mma16816(b1, fqh[ks], bh + 2);
            }
            const int pc   = npi * 16 + tg * 2;
            const int cidx = np * 16 + tg * 2;
            float* pr0 = pos + (w * 16 + g) * POSW2;
            float* pr1 = pos + (w * 16 + g + 8) * POSW2;
            const float ca = c2s[cidx],     cb = c2s[cidx + 1];
            const float cd = c2s[cidx + 8], ce = c2s[cidx + 9];
            *(float2*)(pr0 + pc)     = make_float2(b0[0] + ca, b0[1] + cb);
            *(float2*)(pr1 + pc)     = make_float2(b0[2] + ca, b0[3] + cb);
            *(float2*)(pr0 + pc + 8) = make_float2(b1[0] + cd, b1[1] + ce);
            *(float2*)(pr1 + pc + 8) = make_float2(b1[2] + cd, b1[3] + ce);
        }

        float sfr[8][4] = {};
#pragma unroll
        for (int ks = 0; ks < 4; ks++) {
#pragma unroll
            for (int np = 0; np < 4; np++) {
                uint32_t bh[4];
                ldmx4(bh, uK + (np * 16 + brow) * AST + bk16 + ks * 32);
                mma16816(sfr[np * 2 + 0], fqh[ks], bh + 0);
                mma16816(sfr[np * 2 + 1], fqh[ks], bh + 2);
            }
        }
        __syncwarp();

#pragma unroll
        for (int r2 = 0; r2 < 2; r2++) {
            const int ii = g + r2 * 8;
            const float* pr = pos + (w * 16 + ii) * POSW2 + (15 - ii);
            float mx = -INFINITY;
#pragma unroll
            for (int nt = 0; nt < 8; nt++) {
#pragma unroll
                for (int v2 = 0; v2 < 2; v2++) {
                    const int j = nt * 8 + tg * 2 + v2;
                    float t = fmaf(sfr[nt][r2 * 2 + v2] + pr[j], SCALE2F, cc[j]);
                    sfr[nt][r2 * 2 + v2] = t;
                    mx = fmaxf(mx, t);
                }
            }
            mx = fmaxf(mx, __shfl_xor_sync(0xffffffffu, mx, 1));
            mx = fmaxf(mx, __shfl_xor_sync(0xffffffffu, mx, 2));
            const float mnew = fmaxf(mrow[r2], mx);
            const float alpha = exp2p(mrow[r2] - mnew);
            mrow[r2] = mnew;
            float ssum = 0.f;
#pragma unroll
            for (int nt = 0; nt < 8; nt++) {
#pragma unroll
                for (int v2 = 0; v2 < 2; v2++) {
                    float p = exp2p(sfr[nt][r2 * 2 + v2] - mnew);
                    sfr[nt][r2 * 2 + v2] = p;
                    ssum += p;
                }
            }
            ssum += __shfl_xor_sync(0xffffffffu, ssum, 1);
            ssum += __shfl_xor_sync(0xffffffffu, ssum, 2);
            lrowv[r2] = lrowv[r2] * alpha + ssum;
#pragma unroll
            for (int ht = 0; ht < 8; ht++) {
                o[ht][r2 * 2 + 0] *= alpha;
                o[ht][r2 * 2 + 1] *= alpha;
            }
        }

#pragma unroll
        for (int ks = 0; ks < 4; ks++) {
            uint32_t aph[4];
#pragma unroll
            for (int q2 = 0; q2 < 2; q2++) {
                const float* f = sfr[2 * ks + q2];
                aph[q2 * 2 + 0] = pack_h2(f[0], f[1]);
                aph[q2 * 2 + 1] = pack_h2(f[2], f[3]);
            }
            const uint32_t vo = (ks * 16 + vrow) * AST + vsel;
#pragma unroll
            for (int hp = 0; hp < 4; hp++) {
                uint32_t vbh[4];
                ldmx4t(vbh, uV + vo + hp * 32);
                mma16816(o[hp * 2 + 0], aph, vbh + 0);
                mma16816(o[hp * 2 + 1], aph, vbh + 2);
            }
        }
    }

#pragma unroll
    for (int r2 = 0; r2 < 2; r2++) {
        const int i = w * 16 + g + r2 * 8;
        const int rowg = b * LL + l0 + i;
        const float inv = 1.0f / lrowv[r2];
#pragma unroll
        for (int ht = 0; ht < 8; ht++) {
            float v0 = o[ht][r2 * 2 + 0] * inv;
            float v1 = o[ht][r2 * 2 + 1] * inv;
            const int col = n * 64 + ht * 8 + tg * 2;
            outp[(size_t)rowg * 512 + (col >> 1)] = pack_h2(v0, v1);
        }
    }
}

// ---------------------------------------------------------------------------
// LayerNorm
// ---------------------------------------------------------------------------
__global__ __launch_bounds__(256) void ln_kernel(
    float* __restrict__ X, const float* __restrict__ g, const float* __restrict__ bta)
{
    __shared__ float red[8];
    const int row = blockIdx.x;
    const int t   = threadIdx.x;
    float4 x = *(float4*)(X + (size_t)row * DD + t * 4);

    float s = x.x + x.y + x.z + x.w;
#pragma unroll
    for (int d = 16; d; d >>= 1) s += __shfl_xor_sync(0xffffffffu, s, d);
    if ((t & 31) == 0) red[t >> 5] = s;
    __syncthreads();
    float tot = red[0] + red[1] + red[2] + red[3] + red[4] + red[5] + red[6] + red[7];
    float mu = tot * (1.0f / DD);
    __syncthreads();

    float dx0 = x.x - mu, dx1 = x.y - mu, dx2 = x.z - mu, dx3 = x.w - mu;
    float sq = dx0 * dx0 + dx1 * dx1 + dx2 * dx2 + dx3 * dx3;
#pragma unroll
    for (int d = 16; d; d >>= 1) sq += __shfl_xor_sync(0xffffffffu, sq, d);
    if ((t & 31) == 0) red[t >> 5] = sq;
    __syncthreads();
    float var = (red[0] + red[1] + red[2] + red[3] + red[4] + red[5] + red[6] + red[7]) * (1.0f / DD);
    float rs = rsqrtf(var + 1e-5f);

    float4 gg = *(const float4*)(g + t * 4);
    float4 bb = *(const float4*)(bta + t * 4);
    float4 y = make_float4(dx0 * rs * gg.x + bb.x, dx1 * rs * gg.y + bb.y,
                           dx2 * rs * gg.z + bb.z, dx3 * rs * gg.w + bb.w);
    *(float4*)(X + (size_t)row * DD + t * 4) = y;
}

// ---------------------------------------------------------------------------
// Launch
// ---------------------------------------------------------------------------
extern "C" void kernel_launch(void* const* d_in, const int* in_sizes, int n_in,
                              void* d_out, int out_size)
{
    const float* q   = (const float*)d_in[0];
    const float* k   = (const float*)d_in[1];
    const float* v   = (const float*)d_in[2];
    const float* pe  = (const float*)d_in[3];
    const int*   pad = (const int*)d_in[4];
    const float* q_w = (const float*)d_in[5];
    const float* k_w = (const float*)d_in[6];
    const float* k_b = (const float*)d_in[7];
    const float* v_w = (const float*)d_in[8];
    const float* v_b = (const float*)d_in[9];
    const float* rwb = (const float*)d_in[10];
    const float* rrb = (const float*)d_in[11];
    const float* r_k = (const float*)d_in[12];
    const float* pw  = (const float*)d_in[13];
    const float* pb  = (const float*)d_in[14];
    const float* lg  = (const float*)d_in[15];
    const float* lb  = (const float*)d_in[16];
    float* out = (float*)d_out;

    cudaFuncSetAttribute(attn2, cudaFuncAttributeMaxDynamicSharedMemorySize, ATTN_BYTES);

    char *ap, *pep, *inp, *wtp;
    cudaGetSymbolAddress((void**)&ap,  g_A4);
    cudaGetSymbolAddress((void**)&pep, g_PE4);
    cudaGetSymbolAddress((void**)&inp, g_IN4);
    cudaGetSymbolAddress((void**)&wtp, g_WT4);
    uint32_t *qh2, *kh2, *vh2, *rp2;
    float *c1p, *c2p;
    cudaGetSymbolAddress((void**)&qh2, g_QH2);
    cudaGetSymbolAddress((void**)&kh2, g_KH2);
    cudaGetSymbolAddress((void**)&vh2, g_VH2);
    cudaGetSymbolAddress((void**)&rp2, g_RP2);
    cudaGetSymbolAddress((void**)&c1p, g_C1);
    cudaGetSymbolAddress((void**)&c2p, g_C2);

    dim3 tr(32, 8);

    // 1. conversions + weight transposes (independent, batched)
    cvt4_kernel<<<dim3(4096, 1, 4), 256>>>((const float4*)q, (const float4*)k,
                                           (const float4*)v, (const float4*)pe,
                                           (uint32_t*)ap, (uint32_t*)pep);
    trcvt4_kernel<<<dim3(32, 32, 4), tr>>>(q_w, k_w, v_w, pw, (__half*)wtp);
    trcvt_kernel<<<dim3(2, 32, 16), tr>>>(r_k, (__half*)wtp + (size_t)4 * DD * DD, DD, HH);
    // 2. qkv projections, batched
    hgemm<<<dim3(8, 32, 3), 256>>>(ap, nullptr, nullptr, (const __half*)wtp,
                                   k_b, v_b, nullptr, nullptr, nullptr,
                                   qh2, kh2, vh2, 0);
    cdot_kernel<<<BB * NH * LL / 256, 256>>>(kh2, rwb, c1p, 10);
    // 3. rp projection
    hgemm<<<dim3(8, 16, 1), 256>>>(nullptr, nullptr, pep, (const __half*)wtp,
                                   nullptr, nullptr, nullptr, nullptr, nullptr,
                                   rp2, nullptr, nullptr, 4);
    cdot_kernel<<<NH * RR / 256, 256>>>(rp2, rrb, c2p, 11);
    // 4. attention
    attn2<<<dim3(LL / 128, BB * NH), 256, ATTN_BYTES>>>(pad, c1p, c2p, qh2,
                                                        kh2, vh2, rp2,
                                                        (uint32_t*)inp);
    // 5. post projection + residual
    hgemm<<<dim3(8, 32, 1), 256>>>(nullptr, inp, nullptr, (const __half*)wtp,
                                   nullptr, nullptr, pb, q, out,
                                   nullptr, nullptr, nullptr, 3);
    // 6. layernorm
    ln_kernel<<<BB * LL, 256>>>(out, lg, lb);
}

// round 17
// speedup vs baseline: 1.3291x; 1.1179x over previous
#include <cuda_runtime.h>
#include <cuda_fp16.h>
#include <math.h>
#include <stdint.h>

// Problem constants
#define BB   4
#define LL   1024
#define DD   1024
#define NH   16
#define HH   64
#define RR   2048
#define LOG2E 1.4426950408889634f
#define KBYTES 2048        // K=1024 fp16 row stride in bytes

// ---------------------------------------------------------------------------
// Device scratch
// ---------------------------------------------------------------------------
__device__ uint4 g_A4[3 * BB * LL * DD / 8];   // 24 MB: fp16 q,k,v activations
__device__ uint4 g_PE4[RR * DD / 8];           // 4 MB: fp16 pos_enc
__device__ uint4 g_IN4[BB * LL * DD / 8];      // 8 MB: fp16 attn output
__device__ uint4 g_WT4[5 * DD * DD / 8];       // 10 MB fp16 weights, 5 slots [n][k]

__device__ uint32_t g_QH2[BB * NH * LL * HH / 2];
__device__ uint32_t g_KH2[BB * NH * LL * HH / 2];
__device__ uint32_t g_VH2[BB * NH * LL * HH / 2];
__device__ uint32_t g_RP2[NH * RR * HH / 2];
__device__ float    g_C1[BB * NH * LL];
__device__ float    g_C2[NH * RR];

__device__ __forceinline__ uint32_t smem_u32(const void* p) {
    uint32_t a;
    asm("{ .reg .u64 t; cvta.to.shared.u64 t, %1; cvt.u32.u64 %0, t; }" : "=r"(a) : "l"(p));
    return a;
}
__device__ __forceinline__ void ldmx4(uint32_t* r, uint32_t addr) {
    asm volatile("ldmatrix.sync.aligned.m8n8.x4.shared.b16 {%0,%1,%2,%3}, [%4];"
        : "=r"(r[0]), "=r"(r[1]), "=r"(r[2]), "=r"(r[3]) : "r"(addr));
}
__device__ __forceinline__ void ldmx4t(uint32_t* r, uint32_t addr) {
    asm volatile("ldmatrix.sync.aligned.m8n8.x4.trans.shared.b16 {%0,%1,%2,%3}, [%4];"
        : "=r"(r[0]), "=r"(r[1]), "=r"(r[2]), "=r"(r[3]) : "r"(addr));
}
__device__ __forceinline__ void mma16816(float* c, const uint32_t* a, const uint32_t* b) {
    asm volatile("mma.sync.aligned.m16n8k16.row.col.f32.f16.f16.f32 "
        "{%0,%1,%2,%3}, {%4,%5,%6,%7}, {%8,%9}, {%0,%1,%2,%3};"
        : "+f"(c[0]), "+f"(c[1]), "+f"(c[2]), "+f"(c[3])
        : "r"(a[0]), "r"(a[1]), "r"(a[2]), "r"(a[3]), "r"(b[0]), "r"(b[1]));
}
#define CPA16(dst, src) \
    asm volatile("cp.async.cg.shared.global [%0], [%1], 16;" :: "r"(dst), "l"(src) : "memory")
#define CPA16CA(dst, src) \
    asm volatile("cp.async.ca.shared.global [%0], [%1], 16;" :: "r"(dst), "l"(src) : "memory")
#define CP_COMMIT() asm volatile("cp.async.commit_group;" ::: "memory")
#define CP_WAIT(n)  asm volatile("cp.async.wait_group %0;" :: "n"(n) : "memory")

__device__ __forceinline__ uint32_t pack_h2(float a, float b) {
    __half2 h2; h2.x = __float2half_rn(a); h2.y = __float2half_rn(b);
    return *(uint32_t*)&h2;
}
// exp2 on FMA pipe: deg-5 poly + exponent splice.  arg <= 0, clamped at -125.
__device__ __forceinline__ float exp2p(float t) {
    t = fmaxf(t, -125.0f);
    float tr = t + 12582912.0f;
    int   n  = __float_as_int(tr) - 0x4B400000;
    float f  = t - (tr - 12582912.0f);
    float p  = 1.3333558146e-3f;
    p = fmaf(p, f, 9.6181291076e-3f);
    p = fmaf(p, f, 5.5504108665e-2f);
    p = fmaf(p, f, 2.4022650696e-1f);
    p = fmaf(p, f, 6.9314718056e-1f);
    p = fmaf(p, f, 1.0f);
    return __int_as_float(__float_as_int(p) + (n << 23));
}

// ---------------------------------------------------------------------------
// Prepass: batched fp32 -> fp16 conversion
// ---------------------------------------------------------------------------
__global__ __launch_bounds__(256) void cvt4_kernel(
    const float4* __restrict__ s0, const float4* __restrict__ s1,
    const float4* __restrict__ s2, const float4* __restrict__ s3,
    uint32_t* __restrict__ abase, uint32_t* __restrict__ pebase)
{
    const int z = blockIdx.z;
    const int n4 = (z < 3) ? (BB * LL * DD / 4) : (RR * DD / 4);
    int i = blockIdx.x * 256 + threadIdx.x;
    if (i >= n4) return;
    const float4* src = (z == 0) ? s0 : (z == 1) ? s1 : (z == 2) ? s2 : s3;
    uint32_t* dst = (z < 3) ? (abase + (size_t)z * (BB * LL * DD / 2)) : pebase;
    float4 x = src[i];
    dst[i * 2 + 0] = pack_h2(x.x, x.y);
    dst[i * 2 + 1] = pack_h2(x.z, x.w);
}

// Batched square weight transposes
__global__ void trcvt4_kernel(const float* __restrict__ w0, const float* __restrict__ w1,
                              const float* __restrict__ w2, const float* __restrict__ w3,
                              __half* __restrict__ dbase)
{
    __shared__ float t[32][33];
    const int bz = blockIdx.z;
    const float* s = (bz == 0) ? w0 : (bz == 1) ? w1 : (bz == 2) ? w2 : w3;
    __half* d = dbase + (size_t)bz * DD * DD;
    const int c0 = blockIdx.x * 32, r0 = blockIdx.y * 32;
    const int tx = threadIdx.x, ty = threadIdx.y;
#pragma unroll
    for (int i = 0; i < 4; i++)
        t[ty + 8 * i][tx] = s[(size_t)(r0 + ty + 8 * i) * DD + c0 + tx];
    __syncthreads();
#pragma unroll
    for (int i = 0; i < 4; i++)
        d[(size_t)(c0 + ty + 8 * i) * DD + r0 + tx] = __float2half_rn(t[tx][ty + 8 * i]);
}

__global__ void trcvt_kernel(const float* __restrict__ src,
                             __half* __restrict__ dstv, int R, int C)
{
    __shared__ float t[32][33];
    const int bz = blockIdx.z;
    const int c0 = blockIdx.x * 32, r0 = blockIdx.y * 32;
    const int tx = threadIdx.x, ty = threadIdx.y;
    const float* s = src + (size_t)bz * R * C;
#pragma unroll
    for (int i = 0; i < 4; i++)
        t[ty + 8 * i][tx] = s[(size_t)(r0 + ty + 8 * i) * C + c0 + tx];
    __syncthreads();
#pragma unroll
    for (int i = 0; i < 4; i++) {
        float v = t[tx][ty + 8 * i];
        size_t o = (size_t)bz * C * R + (size_t)(c0 + ty + 8 * i) * R + r0 + tx;
        dstv[o] = __float2half_rn(v);
    }
}

// Bias-correction dot products
__global__ __launch_bounds__(256) void cdot_kernel(
    const uint32_t* __restrict__ x2, const float* __restrict__ wvec,
    float* __restrict__ outv, int sel)
{
    __shared__ float w[64];
    const int row = blockIdx.x * 256 + threadIdx.x;
    const int n = (sel == 10) ? ((row >> 10) & 15) : (row >> 11);
    if (threadIdx.x < 64) w[threadIdx.x] = wvec[n * 64 + threadIdx.x];
    __syncthreads();
    float s = 0.f;
    const uint32_t* ph = x2 + (size_t)row * 32;
#pragma unroll 8
    for (int i = 0; i < 32; i++) {
        uint32_t h = ph[i];
        __half2 hb = *(__half2*)&h;
        s += __half2float(hb.x) * w[i * 2] + __half2float(hb.y) * w[i * 2 + 1];
    }
    outv[row] = s;
}

// ---------------------------------------------------------------------------
// HMMA GEMM fp16, 3-stage cp.async ring, 1 barrier per K-chunk, 2 CTA/SM.
// Stage layout: A (128x80)=10240 then B=10240; stage stride 20480.
// mode 0: z in 0..2 selects A slot / W slot / out / bias, bnlh half2 epilogue.
// mode 3: A = Ah (attn output), W slot 3, fp32 out = D + pb + resid.
// mode 4: A = pe16, W slot 4, rp layout half2 epilogue.
// ---------------------------------------------------------------------------
#define STRIDE 80
#define HG_STAGE 20480
#define HG_SMEM (3 * HG_STAGE)

__global__ __launch_bounds__(256, 2) void hgemm(
    const char* __restrict__ Abase, const char* __restrict__ Ah,
    const char* __restrict__ Pe16, const __half* __restrict__ Wb,
    const float* __restrict__ x1, const float* __restrict__ x2,
    const float* __restrict__ pb, const float* __restrict__ resid,
    float* __restrict__ out0,
    uint32_t* __restrict__ o0, uint32_t* __restrict__ o1, uint32_t* __restrict__ o2,
    int mode)
{
    extern __shared__ char hs[];

    const int z = blockIdx.z;
    const int tid = threadIdx.x, lane = tid & 31, wid = tid >> 5;
    const int wm = wid >> 1, wn = wid & 1;
    const int m0 = blockIdx.y * 128, n0 = blockIdx.x * 128;

    const char* Am = (mode == 0) ? (Abase + (size_t)z * (BB * LL * DD * 2))
                   : (mode == 3) ? Ah : Pe16;
    const int wslot = (mode == 0) ? z : (mode == 3 ? 3 : 4);
    const char* Bm  = (const char*)(Wb + (size_t)wslot * DD * DD);

    float c[2][8][4] = {};

    const int lrow = tid >> 1, lseg = (tid & 1) * 32;
    const char* gpA = Am + (size_t)(m0 + lrow) * KBYTES + lseg;
    const char* gpB = Bm + (size_t)(n0 + lrow) * KBYTES + lseg;

    const uint32_t sb = smem_u32(hs);
    const uint32_t stw = sb + lrow * STRIDE + lseg;

    const int arow_in = (lane & 7) + ((lane >> 3) & 1) * 8;
    const int ak16    = (lane >> 4) * 16;
    const int brow_in = (lane & 7) + (lane >> 4) * 8;
    const int bk16    = ((lane >> 3) & 1) * 16;
    const uint32_t aFB = sb + (wm * 32 + arow_in) * STRIDE + ak16;
    const uint32_t bFB = sb + 10240 + (wn * 64 + brow_in) * STRIDE + bk16;

    // prologue: stages 0 and 1 (chunks 0, 1)
#pragma unroll
    for (int s = 0; s < 2; s++) {
        const int off = s * 64;
        const uint32_t d = stw + s * HG_STAGE;
        CPA16CA(d,             gpA + off); CPA16CA(d + 16,             gpA + off + 16);
        CPA16CA(d + 10240,     gpB + off); CPA16CA(d + 10240 + 16,     gpB + off + 16);
        CP_COMMIT();
    }

    int st = 0;
    for (int ck = 0; ck < 32; ck++) {
        if (ck < 31) { CP_WAIT(1); } else { CP_WAIT(0); }
        __syncthreads();
        if (ck + 2 < 32) {
            const int s2 = (st + 2 >= 3) ? st - 1 : st + 2;
            const int off = (ck + 2) * 64;
            const uint32_t d = stw + s2 * HG_STAGE;
            CPA16CA(d,             gpA + off); CPA16CA(d + 16,             gpA + off + 16);
            CPA16CA(d + 10240,     gpB + off); CPA16CA(d + 10240 + 16,     gpB + off + 16);
            CP_COMMIT();
        }

        const uint32_t aOff = aFB + st * HG_STAGE;
        const uint32_t bOff = bFB + st * HG_STAGE;
#pragma unroll
        for (int ks = 0; ks < 2; ks++) {
            const int kb = ks * 32;
            uint32_t ah[2][4];
#pragma unroll
            for (int mt = 0; mt < 2; mt++)
                ldmx4(ah[mt], aOff + mt * (16 * STRIDE) + kb);
#pragma unroll
            for (int ntp = 0; ntp < 4; ntp++) {
                uint32_t bh[4];
                ldmx4(bh, bOff + ntp * (16 * STRIDE) + kb);
#pragma unroll
                for (int mt = 0; mt < 2; mt++) {
                    mma16816(c[mt][ntp * 2 + 0], ah[mt], bh + 0);
                    mma16816(c[mt][ntp * 2 + 1], ah[mt], bh + 2);
                }
            }
        }
        st = (st + 1 == 3) ? 0 : st + 1;
    }

    const float* aux = (mode == 0) ? (z == 0 ? nullptr : (z == 1 ? x1 : x2)) : pb;
    uint32_t* oq = (mode == 0) ? (z == 0 ? o0 : (z == 1 ? o1 : o2)) : o0;

    const int g = lane >> 2, tg = lane & 3;
#pragma unroll
    for (int mt = 0; mt < 2; mt++) {
#pragma unroll
        for (int half = 0; half < 2; half++) {
            const int m = m0 + wm * 32 + mt * 16 + g + half * 8;
#pragma unroll
            for (int nt = 0; nt < 8; nt++) {
                float v0 = c[mt][nt][half * 2 + 0];
                float v1 = c[mt][nt][half * 2 + 1];
                const int coln = n0 + wn * 64 + nt * 8 + tg * 2;
                if (mode == 3) {
                    size_t o = (size_t)m * DD + coln;
                    float2 res = *(const float2*)(resid + o);
                    *(float2*)(out0 + o) =
                        make_float2(v0 + aux[coln] + res.x, v1 + aux[coln + 1] + res.y);
                } else if (mode == 4) {
                    int hd = coln >> 6, h = coln & 63;
                    size_t o = ((size_t)hd * RR + m) * HH + h;
                    oq[o >> 1] = pack_h2(v0, v1);
                } else {
                    int hd = coln >> 6, h = coln & 63;
                    int b = m >> 10, l = m & 1023;
                    size_t o = ((size_t)(b * NH + hd) * LL + l) * HH + h;
                    float b0 = aux ? aux[coln] : 0.f;
                    float b1 = aux ? aux[coln + 1] : 0.f;
                    oq[o >> 1] = pack_h2(v0 + b0, v1 + b1);
                }
            }
        }
    }
}

// ---------------------------------------------------------------------------
// HMMA flash attention (byte-identical to R12/R14)
// ---------------------------------------------------------------------------
#define AST     144
#define POSW2   84
#define OFF_K   0
#define OFF_V   9216
#define OFF_R   18432
#define OFF_POS 46080
#define OFF_CC  89088
#define OFF_C2  89344
#define ATTN_BYTES 90112
#define SCALE2F (0.125f * LOG2E)

__global__ __launch_bounds__(256) void attn2(const int* __restrict__ pad,
    const float* __restrict__ c1g, const float* __restrict__ c2g,
    const uint32_t* __restrict__ qh2, const uint32_t* __restrict__ kh2,
    const uint32_t* __restrict__ vh2, const uint32_t* __restrict__ rp2,
    uint32_t* __restrict__ outp)
{
    extern __shared__ char dyn[];
    float* pos = (float*)(dyn + OFF_POS);
    float* cc  = (float*)(dyn + OFF_CC);
    float* c2s = (float*)(dyn + OFF_C2);

    const int tid = threadIdx.x, lane = tid & 31, w = tid >> 5;
    const int g = lane >> 2, tg = lane & 3;
    const int bn = blockIdx.y, b = bn >> 4, n = bn & 15;
    const int l0 = blockIdx.x * 128;

    const uint32_t uD = smem_u32(dyn);
    const uint32_t uK = uD + OFF_K, uV = uD + OFF_V, uR = uD + OFF_R;

    const int arow = (lane & 7) + ((lane >> 3) & 1) * 8;
    const int ak16 = (lane >> 4) * 16;
    const int brow = (lane & 7) + (lane >> 4) * 8;
    const int bk16 = ((lane >> 3) & 1) * 16;
    const int vrow = (lane & 7) + ((lane >> 3) & 1) * 8;
    const int vsel = (lane >> 4) * 16;

    {
        const int lrowQ = tid >> 1, lsegQ = (tid & 1) * 64;
        const size_t qoff = ((size_t)(bn * LL + l0 + lrowQ) << 7) + lsegQ;
        const uint4* s = (const uint4*)((const char*)qh2 + qoff);
        uint4* d = (uint4*)(dyn + OFF_R + lrowQ * AST + lsegQ);
        d[0] = s[0]; d[1] = s[1]; d[2] = s[2]; d[3] = s[3];
    }
    __syncthreads();
    uint32_t fqh[4][4];
    {
        const uint32_t ao = uR + (w * 16 + arow) * AST + ak16;
#pragma unroll
        for (int ks = 0; ks < 4; ks++)
            ldmx4(fqh[ks], ao + ks * 32);
    }

    float o[8][4] = {};
    float mrow[2] = {-INFINITY, -INFINITY};
    float lrowv[2] = {0.f, 0.f};

    for (int kt = 0; kt < LL / 64; kt++) {
        const int m0 = kt * 64;
        const int rel0 = LL + m0 - l0 - 127;
        const int roff = (kt % 3) * 64;

        __syncthreads();
        {
            const int lrow4 = tid >> 2, lseg4 = (tid & 3) * 32;
            const size_t kv = ((size_t)(bn * LL + m0 + lrow4) << 7) + lseg4;
            const uint32_t dr = uD + lrow4 * AST + lseg4;
            const char* s;
            s = (const char*)kh2 + kv;
            CPA16(dr + OFF_K, s); CPA16(dr + OFF_K + 16, s + 16);
            s = (const char*)vh2 + kv;
            CPA16(dr + OFF_V, s); CPA16(dr + OFF_V + 16, s + 16);
            if (kt == 0) {
#pragma unroll
                for (int cch = 0; cch < 3; cch++) {
                    const int rowl = cch * 64 + lrow4;
                    int rel = rel0 + rowl;
                    rel = rel < 0 ? 0 : (rel > RR - 1 ? RR - 1 : rel);
                    const char* rs = (const char*)rp2 + (((size_t)(n * RR + rel)) << 7) + lseg4;
                    uint32_t rd = uR + rowl * AST + lseg4;
                    CPA16(rd, rs); CPA16(rd + 16, rs + 16);
                }
            } else {
                int rel = rel0 + 128 + lrow4;
                rel = rel < 0 ? 0 : (rel > RR - 1 ? RR - 1 : rel);
                const int phys = (128 + roff) % 192 + lrow4;
                const char* rs = (const char*)rp2 + (((size_t)(n * RR + rel)) << 7) + lseg4;
                uint32_t rd = uR + phys * AST + lseg4;
                CPA16(rd, rs); CPA16(rd + 16, rs + 16);
            }
            CP_COMMIT();
            if (tid < 64)
                cc[tid] = c1g[(size_t)bn * LL + m0 + tid] * SCALE2F +
                          (pad[b * LL + m0 + tid] ? (-1.0e6f * LOG2E) : 0.0f);
            if (tid < 192) {
                int rel = rel0 + tid;
                rel = rel < 0 ? 0 : (rel > RR - 1 ? RR - 1 : rel);
                c2s[tid] = c2g[n * RR + rel];
            }
        }
        CP_WAIT(0);
        __syncthreads();

#pragma unroll
        for (int npi = 0; npi < 5; npi++) {
            const int np = npi + 7 - w;
            float b0[4] = {}, b1[4] = {};
            int pr16 = np * 16 + roff;
            if (pr16 >= 192) pr16 -= 192;
            const uint32_t rbase = (pr16 + brow) * AST + bk16;
#pragma unroll
            for (int ks = 0; ks < 4; ks++) {
                uint32_t bh[4];
                ldmx4(bh, uR + rbase + ks * 32);
                mma16816(b0, fqh[ks], bh + 0);
                mma16816(b1, fqh[ks], bh + 2);
            }
            const int pc   = npi * 16 + tg * 2;
            const int cidx = np * 16 + tg * 2;
            float* pr0 = pos + (w * 16 + g) * POSW2;
            float* pr1 = pos + (w * 16 + g + 8) * POSW2;
            const float ca = c2s[cidx],     cb = c2s[cidx + 1];
            const float cd = c2s[cidx + 8], ce = c2s[cidx + 9];
            *(float2*)(pr0 + pc)     = make_float2(b0[0] + ca, b0[1] + cb);
            *(float2*)(pr1 + pc)     = make_float2(b0[2] + ca, b0[3] + cb);
            *(float2*)(pr0 + pc + 8) = make_float2(b1[0] + cd, b1[1] + ce);
            *(float2*)(pr1 + pc + 8) = make_float2(b1[2] + cd, b1[3] + ce);
        }

        float sfr[8][4] = {};
#pragma unroll
        for (int ks = 0; ks < 4; ks++) {
#pragma unroll
            for (int np = 0; np < 4; np++) {
                uint32_t bh[4];
                ldmx4(bh, uK + (np * 16 + brow) * AST + bk16 + ks * 32);
                mma16816(sfr[np * 2 + 0], fqh[ks], bh + 0);
                mma16816(sfr[np * 2 + 1], fqh[ks], bh + 2);
            }
        }
        __syncwarp();

#pragma unroll
        for (int r2 = 0; r2 < 2; r2++) {
            const int ii = g + r2 * 8;
            const float* pr = pos + (w * 16 + ii) * POSW2 + (15 - ii);
            float mx = -INFINITY;
#pragma unroll
            for (int nt = 0; nt < 8; nt++) {
#pragma unroll
                for (int v2 = 0; v2 < 2; v2++) {
                    const int j = nt * 8 + tg * 2 + v2;
                    float t = fmaf(sfr[nt][r2 * 2 + v2] + pr[j], SCALE2F, cc[j]);
                    sfr[nt][r2 * 2 + v2] = t;
                    mx = fmaxf(mx, t);
                }
            }
            mx = fmaxf(mx, __shfl_xor_sync(0xffffffffu, mx, 1));
            mx = fmaxf(mx, __shfl_xor_sync(0xffffffffu, mx, 2));
            const float mnew = fmaxf(mrow[r2], mx);
            const float alpha = exp2p(mrow[r2] - mnew);
            mrow[r2] = mnew;
            float ssum = 0.f;
#pragma unroll
            for (int nt = 0; nt < 8; nt++) {
#pragma unroll
                for (int v2 = 0; v2 < 2; v2++) {
                    float p = exp2p(sfr[nt][r2 * 2 + v2] - mnew);
                    sfr[nt][r2 * 2 + v2] = p;
                    ssum += p;
                }
            }
            ssum += __shfl_xor_sync(0xffffffffu, ssum, 1);
            ssum += __shfl_xor_sync(0xffffffffu, ssum, 2);
            lrowv[r2] = lrowv[r2] * alpha + ssum;
#pragma unroll
            for (int ht = 0; ht < 8; ht++) {
                o[ht][r2 * 2 + 0] *= alpha;
                o[ht][r2 * 2 + 1] *= alpha;
            }
        }

#pragma unroll
        for (int ks = 0; ks < 4; ks++) {
            uint32_t aph[4];
#pragma unroll
            for (int q2 = 0; q2 < 2; q2++) {
                const float* f = sfr[2 * ks + q2];
                aph[q2 * 2 + 0] = pack_h2(f[0], f[1]);
                aph[q2 * 2 + 1] = pack_h2(f[2], f[3]);
            }
            const uint32_t vo = (ks * 16 + vrow) * AST + vsel;
#pragma unroll
            for (int hp = 0; hp < 4; hp++) {
                uint32_t vbh[4];
                ldmx4t(vbh, uV + vo + hp * 32);
                mma16816(o[hp * 2 + 0], aph, vbh + 0);
                mma16816(o[hp * 2 + 1], aph, vbh + 2);
            }
        }
    }

#pragma unroll
    for (int r2 = 0; r2 < 2; r2++) {
        const int i = w * 16 + g + r2 * 8;
        const int rowg = b * LL + l0 + i;
        const float inv = 1.0f / lrowv[r2];
#pragma unroll
        for (int ht = 0; ht < 8; ht++) {
            float v0 = o[ht][r2 * 2 + 0] * inv;
            float v1 = o[ht][r2 * 2 + 1] * inv;
            const int col = n * 64 + ht * 8 + tg * 2;
            outp[(size_t)rowg * 512 + (col >> 1)] = pack_h2(v0, v1);
        }
    }
}

// ---------------------------------------------------------------------------
// LayerNorm
// ---------------------------------------------------------------------------
__global__ __launch_bounds__(256) void ln_kernel(
    float* __restrict__ X, const float* __restrict__ g, const float* __restrict__ bta)
{
    __shared__ float red[8];
    const int row = blockIdx.x;
    const int t   = threadIdx.x;
    float4 x = *(float4*)(X + (size_t)row * DD + t * 4);

    float s = x.x + x.y + x.z + x.w;
#pragma unroll
    for (int d = 16; d; d >>= 1) s += __shfl_xor_sync(0xffffffffu, s, d);
    if ((t & 31) == 0) red[t >> 5] = s;
    __syncthreads();
    float tot = red[0] + red[1] + red[2] + red[3] + red[4] + red[5] + red[6] + red[7];
    float mu = tot * (1.0f / DD);
    __syncthreads();

    float dx0 = x.x - mu, dx1 = x.y - mu, dx2 = x.z - mu, dx3 = x.w - mu;
    float sq = dx0 * dx0 + dx1 * dx1 + dx2 * dx2 + dx3 * dx3;
#pragma unroll
    for (int d = 16; d; d >>= 1) sq += __shfl_xor_sync(0xffffffffu, sq, d);
    if ((t & 31) == 0) red[t >> 5] = sq;
    __syncthreads();
    float var = (red[0] + red[1] + red[2] + red[3] + red[4] + red[5] + red[6] + red[7]) * (1.0f / DD);
    float rs = rsqrtf(var + 1e-5f);

    float4 gg = *(const float4*)(g + t * 4);
    float4 bb = *(const float4*)(bta + t * 4);
    float4 y = make_float4(dx0 * rs * gg.x + bb.x, dx1 * rs * gg.y + bb.y,
                           dx2 * rs * gg.z + bb.z, dx3 * rs * gg.w + bb.w);
    *(float4*)(X + (size_t)row * DD + t * 4) = y;
}

// ---------------------------------------------------------------------------
// Launch
// ---------------------------------------------------------------------------
extern "C" void kernel_launch(void* const* d_in, const int* in_sizes, int n_in,
                              void* d_out, int out_size)
{
    const float* q   = (const float*)d_in[0];
    const float* k   = (const float*)d_in[1];
    const float* v   = (const float*)d_in[2];
    const float* pe  = (const float*)d_in[3];
    const int*   pad = (const int*)d_in[4];
    const float* q_w = (const float*)d_in[5];
    const float* k_w = (const float*)d_in[6];
    const float* k_b = (const float*)d_in[7];
    const float* v_w = (const float*)d_in[8];
    const float* v_b = (const float*)d_in[9];
    const float* rwb = (const float*)d_in[10];
    const float* rrb = (const float*)d_in[11];
    const float* r_k = (const float*)d_in[12];
    const float* pw  = (const float*)d_in[13];
    const float* pb  = (const float*)d_in[14];
    const float* lg  = (const float*)d_in[15];
    const float* lb  = (const float*)d_in[16];
    float* out = (float*)d_out;

    cudaFuncSetAttribute(attn2, cudaFuncAttributeMaxDynamicSharedMemorySize, ATTN_BYTES);
    cudaFuncSetAttribute(hgemm, cudaFuncAttributeMaxDynamicSharedMemorySize, HG_SMEM);

    char *ap, *pep, *inp, *wtp;
    cudaGetSymbolAddress((void**)&ap,  g_A4);
    cudaGetSymbolAddress((void**)&pep, g_PE4);
    cudaGetSymbolAddress((void**)&inp, g_IN4);
    cudaGetSymbolAddress((void**)&wtp, g_WT4);
    uint32_t *qh2, *kh2, *vh2, *rp2;
    float *c1p, *c2p;
    cudaGetSymbolAddress((void**)&qh2, g_QH2);
    cudaGetSymbolAddress((void**)&kh2, g_KH2);
    cudaGetSymbolAddress((void**)&vh2, g_VH2);
    cudaGetSymbolAddress((void**)&rp2, g_RP2);
    cudaGetSymbolAddress((void**)&c1p, g_C1);
    cudaGetSymbolAddress((void**)&c2p, g_C2);

    dim3 tr(32, 8);

    // 1. conversions + weight transposes (independent, batched)
    cvt4_kernel<<<dim3(4096, 1, 4), 256>>>((const float4*)q, (const float4*)k,
                                           (const float4*)v, (const float4*)pe,
                                           (uint32_t*)ap, (uint32_t*)pep);
    trcvt4_kernel<<<dim3(32, 32, 4), tr>>>(q_w, k_w, v_w, pw, (__half*)wtp);
    trcvt_kernel<<<dim3(2, 32, 16), tr>>>(r_k, (__half*)wtp + (size_t)4 * DD * DD, DD, HH);
    // 2. qkv projections, batched
    hgemm<<<dim3(8, 32, 3), 256, HG_SMEM>>>(ap, nullptr, nullptr, (const __half*)wtp,
                                            k_b, v_b, nullptr, nullptr, nullptr,
                                            qh2, kh2, vh2, 0);
    cdot_kernel<<<BB * NH * LL / 256, 256>>>(kh2, rwb, c1p, 10);
    // 3. rp projection
    hgemm<<<dim3(8, 16, 1), 256, HG_SMEM>>>(nullptr, nullptr, pep, (const __half*)wtp,
                                            nullptr, nullptr, nullptr, nullptr, nullptr,
                                            rp2, nullptr, nullptr, 4);
    cdot_kernel<<<NH * RR / 256, 256>>>(rp2, rrb, c2p, 11);
    // 4. attention
    attn2<<<dim3(LL / 128, BB * NH), 256, ATTN_BYTES>>>(pad, c1p, c2p, qh2,
                                                        kh2, vh2, rp2,
                                                        (uint32_t*)inp);
    // 5. post projection + residual
    hgemm<<<dim3(8, 32, 1), 256, HG_SMEM>>>(nullptr, inp, nullptr, (const __half*)wtp,
                                            nullptr, nullptr, pb, q, out,
                                            nullptr, nullptr, nullptr, 3);
    // 6. layernorm
    ln_kernel<<<BB * LL, 256>>>(out, lg, lb);
}